// round 3
// baseline (speedup 1.0000x reference)
#include <cuda_runtime.h>
#include <cuda_bf16.h>

#define N_NODES 100000
#define N_EDGES 1600000
#define IN_DIM  128
#define OUT_DIM 64
#define NEG_SLOPE 0.2f

// Scratch (static device globals — no allocation allowed)
__device__ __align__(16) float g_Wh[(size_t)N_NODES * OUT_DIM];
__device__ float g_ssrc[N_NODES];
__device__ float g_sdst[N_NODES];
__device__ float g_w[N_EDGES];
__device__ float g_denom[N_NODES];

// ---------------------------------------------------------------------------
// K0: zero out[] and g_denom (avoids memset-on-symbol during graph capture)
// ---------------------------------------------------------------------------
__global__ void init_kernel(float* __restrict__ out) {
    const int total4 = (N_NODES * OUT_DIM) / 4;   // 1.6M float4
    int i = blockIdx.x * blockDim.x + threadIdx.x;
    int stride = gridDim.x * blockDim.x;
    float4 z = make_float4(0.f, 0.f, 0.f, 0.f);
    for (int k = i; k < total4; k += stride) ((float4*)out)[k] = z;
    for (int k = i; k < N_NODES; k += stride) g_denom[k] = 0.f;
}

// ---------------------------------------------------------------------------
// K1: Wh = h @ W    (h: [N,128] f32, W: [128,64] f32, Wh: [N,64] f32)
// Block: 256 threads = 16 rows x 16 col-groups (4 cols each as float4).
// ---------------------------------------------------------------------------
__global__ void gemm_kernel(const float* __restrict__ h, const float* __restrict__ W) {
    __shared__ __align__(16) float4 Ws[IN_DIM * 16];       // [k][cg]
    __shared__ __align__(16) float  hs[16][132];           // padded rows

    const int tid  = threadIdx.x;
    const int row0 = blockIdx.x * 16;

    const float4* W4 = (const float4*)W;
    #pragma unroll
    for (int i = 0; i < 8; i++) Ws[tid + i * 256] = W4[tid + i * 256];

    #pragma unroll
    for (int p = 0; p < 2; p++) {
        int idx = tid + p * 256;
        int r = idx >> 5, c4 = idx & 31;
        int node = row0 + r;
        float4 v = make_float4(0.f, 0.f, 0.f, 0.f);
        if (node < N_NODES) v = ((const float4*)h)[(size_t)node * 32 + c4];
        *(float4*)&hs[r][c4 * 4] = v;
    }
    __syncthreads();

    const int cg = tid & 15;
    const int r  = tid >> 4;
    const float* hr = &hs[r][0];

    float4 acc = make_float4(0.f, 0.f, 0.f, 0.f);
    #pragma unroll 16
    for (int k = 0; k < IN_DIM; k++) {
        float hk = hr[k];
        float4 w = Ws[k * 16 + cg];
        acc.x = fmaf(hk, w.x, acc.x);
        acc.y = fmaf(hk, w.y, acc.y);
        acc.z = fmaf(hk, w.z, acc.z);
        acc.w = fmaf(hk, w.w, acc.w);
    }

    int node = row0 + r;
    if (node < N_NODES) ((float4*)g_Wh)[(size_t)node * 16 + cg] = acc;
}

// ---------------------------------------------------------------------------
// K2: s_src[n] = Wh[n,:] . a[0:64],  s_dst[n] = Wh[n,:] . a[64:128]
// One warp per node (grid-stride), 2 elements per lane, shfl reduction.
// ---------------------------------------------------------------------------
__global__ void s_kernel(const float* __restrict__ a) {
    const int lane  = threadIdx.x & 31;
    const int warp  = (blockIdx.x * blockDim.x + threadIdx.x) >> 5;
    const int nwarp = (gridDim.x * blockDim.x) >> 5;

    const float a0s = a[lane],      a1s = a[lane + 32];
    const float a0d = a[64 + lane], a1d = a[96 + lane];

    for (int n = warp; n < N_NODES; n += nwarp) {
        float v0 = g_Wh[(size_t)n * 64 + lane];
        float v1 = g_Wh[(size_t)n * 64 + 32 + lane];
        float ss = v0 * a0s + v1 * a1s;
        float sd = v0 * a0d + v1 * a1d;
        #pragma unroll
        for (int o = 16; o > 0; o >>= 1) {
            ss += __shfl_down_sync(0xFFFFFFFFu, ss, o);
            sd += __shfl_down_sync(0xFFFFFFFFu, sd, o);
        }
        if (lane == 0) { g_ssrc[n] = ss; g_sdst[n] = sd; }
    }
}

// ---------------------------------------------------------------------------
// K3: per-edge unnormalized attention weight + denominator accumulation.
// Global max(e) subtraction skipped (cancels to ~1e-9 through the epsilon).
// ---------------------------------------------------------------------------
__global__ void edge_kernel(const int* __restrict__ row,
                            const int* __restrict__ col) {
    int e = blockIdx.x * blockDim.x + threadIdx.x;
    if (e >= N_EDGES) return;
    int r = row[e];
    int c = col[e];
    float x = g_ssrc[r] + g_sdst[c];
    x = (x > 0.f) ? x : NEG_SLOPE * x;
    float w = __expf(x);
    g_w[e] = w;
    atomicAdd(&g_denom[r], w);
}

// ---------------------------------------------------------------------------
// K4: out[row] += (w_e / (denom[row]+1e-10)) * Wh[col]
// 16 threads per edge, one float4 each; red.global.add.v4.f32 into out.
// ---------------------------------------------------------------------------
__global__ void agg_kernel(const int* __restrict__ row,
                           const int* __restrict__ col,
                           float* __restrict__ out) {
    int g = blockIdx.x * blockDim.x + threadIdx.x;
    int e   = g >> 4;
    int sub = g & 15;
    if (e >= N_EDGES) return;

    int r = row[e];
    int c = col[e];
    float alpha = g_w[e] / (g_denom[r] + 1e-10f);

    float4 v = ((const float4*)g_Wh)[(size_t)c * 16 + sub];
    float* dst = out + (size_t)r * 64 + sub * 4;
    asm volatile("red.global.add.v4.f32 [%0], {%1, %2, %3, %4};"
                 :: "l"(dst), "f"(alpha * v.x), "f"(alpha * v.y),
                    "f"(alpha * v.z), "f"(alpha * v.w)
                 : "memory");
}

// ---------------------------------------------------------------------------
extern "C" void kernel_launch(void* const* d_in, const int* in_sizes, int n_in,
                              void* d_out, int out_size) {
    const float* h   = (const float*)d_in[0];
    const int*   row = (const int*)d_in[1];
    const int*   col = (const int*)d_in[2];
    const float* W   = (const float*)d_in[3];
    const float* a   = (const float*)d_in[4];
    float*       out = (float*)d_out;

    init_kernel<<<512, 256>>>(out);
    gemm_kernel<<<(N_NODES + 15) / 16, 256>>>(h, W);
    s_kernel<<<512, 256>>>(a);
    edge_kernel<<<(N_EDGES + 255) / 256, 256>>>(row, col);
    agg_kernel<<<(N_EDGES * 16 + 255) / 256, 256>>>(row, col, out);
}

// round 4
// speedup vs baseline: 1.1307x; 1.1307x over previous
#include <cuda_runtime.h>
#include <cuda_bf16.h>

#define N_NODES 100000
#define N_EDGES 1600000
#define IN_DIM  128
#define OUT_DIM 64
#define NEG_SLOPE 0.2f

#define SCAN_B 1024
#define SCAN_NB ((N_NODES + SCAN_B - 1) / SCAN_B)   // 98

// Scratch (static device globals — no allocation allowed)
__device__ __align__(16) float g_Wh[(size_t)N_NODES * OUT_DIM];
__device__ float g_ssrc[N_NODES];
__device__ float g_sdst[N_NODES];
__device__ int   g_count[N_NODES];
__device__ int   g_rowstart[N_NODES];
__device__ int   g_cursor[N_NODES];
__device__ int   g_bsum[SCAN_NB];
__device__ __align__(8) int2 g_epack[N_EDGES];      // (col, bits(w)) grouped by row

// ---------------------------------------------------------------------------
// K0: zero the histogram
// ---------------------------------------------------------------------------
__global__ void init_kernel() {
    int i = blockIdx.x * blockDim.x + threadIdx.x;
    int stride = gridDim.x * blockDim.x;
    for (int k = i; k < N_NODES; k += stride) g_count[k] = 0;
}

// ---------------------------------------------------------------------------
// K1: Wh = h @ W, fused with s_src = Wh.a[0:64], s_dst = Wh.a[64:128]
// Block: 256 threads = 16 rows x 16 col-groups (float4 each).
// ---------------------------------------------------------------------------
__global__ void gemm_s_kernel(const float* __restrict__ h,
                              const float* __restrict__ W,
                              const float* __restrict__ a) {
    __shared__ __align__(16) float4 Ws[IN_DIM * 16];
    __shared__ __align__(16) float  hs[16][132];

    const int tid  = threadIdx.x;
    const int row0 = blockIdx.x * 16;

    const float4* W4 = (const float4*)W;
    #pragma unroll
    for (int i = 0; i < 8; i++) Ws[tid + i * 256] = W4[tid + i * 256];

    #pragma unroll
    for (int p = 0; p < 2; p++) {
        int idx = tid + p * 256;
        int r = idx >> 5, c4 = idx & 31;
        int node = row0 + r;
        float4 v = make_float4(0.f, 0.f, 0.f, 0.f);
        if (node < N_NODES) v = ((const float4*)h)[(size_t)node * 32 + c4];
        *(float4*)&hs[r][c4 * 4] = v;
    }
    __syncthreads();

    const int cg = tid & 15;
    const int r  = tid >> 4;
    const float* hr = &hs[r][0];

    float4 acc = make_float4(0.f, 0.f, 0.f, 0.f);
    #pragma unroll 16
    for (int k = 0; k < IN_DIM; k++) {
        float hk = hr[k];
        float4 w = Ws[k * 16 + cg];
        acc.x = fmaf(hk, w.x, acc.x);
        acc.y = fmaf(hk, w.y, acc.y);
        acc.z = fmaf(hk, w.z, acc.z);
        acc.w = fmaf(hk, w.w, acc.w);
    }

    int node = row0 + r;
    if (node < N_NODES) ((float4*)g_Wh)[(size_t)node * 16 + cg] = acc;

    // Fused s_src / s_dst: per-row dot with a, reduced across the 16 cgs
    float ss = acc.x * a[cg * 4 + 0] + acc.y * a[cg * 4 + 1]
             + acc.z * a[cg * 4 + 2] + acc.w * a[cg * 4 + 3];
    float sd = acc.x * a[64 + cg * 4 + 0] + acc.y * a[64 + cg * 4 + 1]
             + acc.z * a[64 + cg * 4 + 2] + acc.w * a[64 + cg * 4 + 3];
    #pragma unroll
    for (int o = 8; o > 0; o >>= 1) {
        ss += __shfl_down_sync(0xFFFFFFFFu, ss, o, 16);
        sd += __shfl_down_sync(0xFFFFFFFFu, sd, o, 16);
    }
    if (cg == 0 && node < N_NODES) { g_ssrc[node] = ss; g_sdst[node] = sd; }
}

// ---------------------------------------------------------------------------
// K2: histogram of row ids (4 edges per thread)
// ---------------------------------------------------------------------------
__global__ void hist_kernel(const int* __restrict__ row) {
    int t = blockIdx.x * blockDim.x + threadIdx.x;
    int e4 = t * 4;
    if (e4 + 3 < N_EDGES) {
        int4 r = ((const int4*)row)[t];
        atomicAdd(&g_count[r.x], 1);
        atomicAdd(&g_count[r.y], 1);
        atomicAdd(&g_count[r.z], 1);
        atomicAdd(&g_count[r.w], 1);
    } else {
        for (int e = e4; e < N_EDGES; e++) atomicAdd(&g_count[row[e]], 1);
    }
}

// ---------------------------------------------------------------------------
// K3a/b/c: exclusive scan of g_count -> g_rowstart (and cursor copy)
// ---------------------------------------------------------------------------
__global__ void scan1_kernel() {
    __shared__ int s[SCAN_B];
    int i = blockIdx.x * SCAN_B + threadIdx.x;
    int v = (i < N_NODES) ? g_count[i] : 0;
    s[threadIdx.x] = v;
    __syncthreads();
    int x = v;
    #pragma unroll
    for (int o = 1; o < SCAN_B; o <<= 1) {
        int t = (threadIdx.x >= o) ? s[threadIdx.x - o] : 0;
        __syncthreads();
        x += t;
        s[threadIdx.x] = x;
        __syncthreads();
    }
    if (i < N_NODES) g_rowstart[i] = x - v;          // exclusive within block
    if (threadIdx.x == SCAN_B - 1) g_bsum[blockIdx.x] = x;
}

__global__ void scan2_kernel() {
    if (threadIdx.x == 0) {
        int acc = 0;
        for (int i = 0; i < SCAN_NB; i++) { int t = g_bsum[i]; g_bsum[i] = acc; acc += t; }
    }
}

__global__ void scan3_kernel() {
    int i = blockIdx.x * blockDim.x + threadIdx.x;
    if (i < N_NODES) {
        int v = g_rowstart[i] + g_bsum[i / SCAN_B];
        g_rowstart[i] = v;
        g_cursor[i]   = v;
    }
}

// ---------------------------------------------------------------------------
// K4: per-edge weight + scatter into row-grouped buckets
// ---------------------------------------------------------------------------
__global__ void scatter_kernel(const int* __restrict__ row,
                               const int* __restrict__ col) {
    int e = blockIdx.x * blockDim.x + threadIdx.x;
    if (e >= N_EDGES) return;
    int r = row[e];
    int c = col[e];
    float x = g_ssrc[r] + g_sdst[c];
    x = (x > 0.f) ? x : NEG_SLOPE * x;
    float w = __expf(x);
    int p = atomicAdd(&g_cursor[r], 1);
    g_epack[p] = make_int2(c, __float_as_int(w));
}

// ---------------------------------------------------------------------------
// K5: per-node aggregation. One warp per node; register accumulation.
// denom computed in-warp (no atomics anywhere in the output path).
// ---------------------------------------------------------------------------
__global__ void agg_csr_kernel(float* __restrict__ out) {
    const int warp = (blockIdx.x * blockDim.x + threadIdx.x) >> 5;
    const int lane = threadIdx.x & 31;
    if (warp >= N_NODES) return;

    const int start = g_rowstart[warp];
    const int cnt   = g_count[warp];

    // denominator: lanes sum distinct edges, butterfly reduce
    float dsum = 0.f;
    for (int i = lane; i < cnt; i += 32)
        dsum += __int_as_float(g_epack[start + i].y);
    #pragma unroll
    for (int o = 16; o > 0; o >>= 1)
        dsum += __shfl_xor_sync(0xFFFFFFFFu, dsum, o);
    const float inv = 1.f / (dsum + 1e-10f);

    float2 acc = make_float2(0.f, 0.f);
    for (int base = 0; base < cnt; base += 32) {
        int idx = base + lane;
        int2 p = (idx < cnt) ? g_epack[start + idx] : make_int2(0, 0);
        int m = cnt - base; if (m > 32) m = 32;
        #pragma unroll 4
        for (int j = 0; j < m; j++) {
            int   c = __shfl_sync(0xFFFFFFFFu, p.x, j);
            float w = __int_as_float(__shfl_sync(0xFFFFFFFFu, p.y, j));
            float2 v = ((const float2*)g_Wh)[(size_t)c * 32 + lane];
            float al = w * inv;
            acc.x = fmaf(al, v.x, acc.x);
            acc.y = fmaf(al, v.y, acc.y);
        }
    }
    ((float2*)out)[(size_t)warp * 32 + lane] = acc;   // covers all elements
}

// ---------------------------------------------------------------------------
extern "C" void kernel_launch(void* const* d_in, const int* in_sizes, int n_in,
                              void* d_out, int out_size) {
    const float* h   = (const float*)d_in[0];
    const int*   row = (const int*)d_in[1];
    const int*   col = (const int*)d_in[2];
    const float* W   = (const float*)d_in[3];
    const float* a   = (const float*)d_in[4];
    float*       out = (float*)d_out;

    init_kernel<<<256, 256>>>();
    gemm_s_kernel<<<(N_NODES + 15) / 16, 256>>>(h, W, a);
    hist_kernel<<<(N_EDGES / 4 + 255) / 256, 256>>>(row);
    scan1_kernel<<<SCAN_NB, SCAN_B>>>();
    scan2_kernel<<<1, 32>>>();
    scan3_kernel<<<(N_NODES + 255) / 256, 256>>>();
    scatter_kernel<<<(N_EDGES + 255) / 256, 256>>>(row, col);
    agg_csr_kernel<<<(N_NODES * 32 + 255) / 256, 256>>>(out);
}

// round 5
// speedup vs baseline: 1.6242x; 1.4365x over previous
#include <cuda_runtime.h>
#include <cuda_bf16.h>

#define N_NODES 100000
#define N_EDGES 1600000
#define IN_DIM  128
#define OUT_DIM 64
#define NEG_SLOPE 0.2f

#define SCAN_B 1024
#define SCAN_NB ((N_NODES + SCAN_B - 1) / SCAN_B)   // 98

// Scratch (static device globals — no allocation allowed)
__device__ __align__(16) float g_Wh[(size_t)N_NODES * OUT_DIM];
__device__ float g_ssrc[N_NODES];
__device__ float g_sdst[N_NODES];
__device__ int   g_count[N_NODES];
__device__ int   g_rowstart[N_NODES];
__device__ int   g_cursor[N_NODES];
__device__ int   g_bsum[SCAN_NB];
__device__ __align__(8) int2 g_epack[N_EDGES];      // (col, bits(w)) grouped by row

// ---------------------------------------------------------------------------
// K0: zero the histogram
// ---------------------------------------------------------------------------
__global__ void init_kernel() {
    int i = blockIdx.x * blockDim.x + threadIdx.x;
    int stride = gridDim.x * blockDim.x;
    for (int k = i; k < N_NODES; k += stride) g_count[k] = 0;
}

// ---------------------------------------------------------------------------
// K1: Wh = h @ W fused with s_src/s_dst.
// Register-tiled: block = 256 threads covers 64 rows x 64 cols, each thread
// computes a 4x4 output patch. K processed in 2 chunks of 64.
// smem: hs[64 rows][68] (17.4KB) + Ws[64 k][64 n] (16KB) = 33.4KB.
// ---------------------------------------------------------------------------
__global__ void gemm_s_kernel(const float* __restrict__ h,
                              const float* __restrict__ W,
                              const float* __restrict__ a) {
    __shared__ __align__(16) float hs[64][68];
    __shared__ __align__(16) float Ws[64][64];

    const int tid  = threadIdx.x;
    const int tx   = tid & 15;        // col group (4 cols)
    const int ty   = tid >> 4;        // row group (4 rows)
    const int row0 = blockIdx.x * 64;

    float acc[4][4];
    #pragma unroll
    for (int i = 0; i < 4; i++)
        #pragma unroll
        for (int j = 0; j < 4; j++) acc[i][j] = 0.f;

    #pragma unroll
    for (int kc = 0; kc < 2; kc++) {
        // Load h chunk: 64 rows x 16 float4, 4 per thread
        #pragma unroll
        for (int p = 0; p < 4; p++) {
            int idx = tid + p * 256;
            int r = idx >> 4, c4 = idx & 15;
            int node = row0 + r;
            float4 v = make_float4(0.f, 0.f, 0.f, 0.f);
            if (node < N_NODES)
                v = ((const float4*)h)[(size_t)node * 32 + kc * 16 + c4];
            *(float4*)&hs[r][c4 * 4] = v;
        }
        // Load W chunk: 64 k x 16 float4, 4 per thread
        #pragma unroll
        for (int p = 0; p < 4; p++) {
            int idx = tid + p * 256;
            int k = idx >> 4, n4 = idx & 15;
            *(float4*)&Ws[k][n4 * 4] =
                ((const float4*)W)[(size_t)(kc * 64 + k) * 16 + n4];
        }
        __syncthreads();

        #pragma unroll 8
        for (int k = 0; k < 64; k++) {
            float4 wv = *(const float4*)&Ws[k][tx * 4];
            float h0 = hs[ty * 4 + 0][k];
            float h1 = hs[ty * 4 + 1][k];
            float h2 = hs[ty * 4 + 2][k];
            float h3 = hs[ty * 4 + 3][k];
            acc[0][0] = fmaf(h0, wv.x, acc[0][0]);
            acc[0][1] = fmaf(h0, wv.y, acc[0][1]);
            acc[0][2] = fmaf(h0, wv.z, acc[0][2]);
            acc[0][3] = fmaf(h0, wv.w, acc[0][3]);
            acc[1][0] = fmaf(h1, wv.x, acc[1][0]);
            acc[1][1] = fmaf(h1, wv.y, acc[1][1]);
            acc[1][2] = fmaf(h1, wv.z, acc[1][2]);
            acc[1][3] = fmaf(h1, wv.w, acc[1][3]);
            acc[2][0] = fmaf(h2, wv.x, acc[2][0]);
            acc[2][1] = fmaf(h2, wv.y, acc[2][1]);
            acc[2][2] = fmaf(h2, wv.z, acc[2][2]);
            acc[2][3] = fmaf(h2, wv.w, acc[2][3]);
            acc[3][0] = fmaf(h3, wv.x, acc[3][0]);
            acc[3][1] = fmaf(h3, wv.y, acc[3][1]);
            acc[3][2] = fmaf(h3, wv.z, acc[3][2]);
            acc[3][3] = fmaf(h3, wv.w, acc[3][3]);
        }
        __syncthreads();
    }

    // Write Wh + fused per-row scores
    const float4 as = *(const float4*)&a[tx * 4];
    const float4 ad = *(const float4*)&a[64 + tx * 4];
    float ss[4], sd[4];
    #pragma unroll
    for (int i = 0; i < 4; i++) {
        int node = row0 + ty * 4 + i;
        float4 v = make_float4(acc[i][0], acc[i][1], acc[i][2], acc[i][3]);
        if (node < N_NODES)
            ((float4*)g_Wh)[(size_t)node * 16 + tx] = v;
        ss[i] = v.x * as.x + v.y * as.y + v.z * as.z + v.w * as.w;
        sd[i] = v.x * ad.x + v.y * ad.y + v.z * ad.z + v.w * ad.w;
    }
    #pragma unroll
    for (int o = 8; o > 0; o >>= 1) {
        #pragma unroll
        for (int i = 0; i < 4; i++) {
            ss[i] += __shfl_down_sync(0xFFFFFFFFu, ss[i], o, 16);
            sd[i] += __shfl_down_sync(0xFFFFFFFFu, sd[i], o, 16);
        }
    }
    if (tx == 0) {
        #pragma unroll
        for (int i = 0; i < 4; i++) {
            int node = row0 + ty * 4 + i;
            if (node < N_NODES) { g_ssrc[node] = ss[i]; g_sdst[node] = sd[i]; }
        }
    }
}

// ---------------------------------------------------------------------------
// K2: histogram of row ids (4 edges per thread)
// ---------------------------------------------------------------------------
__global__ void hist_kernel(const int* __restrict__ row) {
    int t = blockIdx.x * blockDim.x + threadIdx.x;
    int e4 = t * 4;
    if (e4 + 3 < N_EDGES) {
        int4 r = ((const int4*)row)[t];
        atomicAdd(&g_count[r.x], 1);
        atomicAdd(&g_count[r.y], 1);
        atomicAdd(&g_count[r.z], 1);
        atomicAdd(&g_count[r.w], 1);
    } else {
        for (int e = e4; e < N_EDGES; e++) atomicAdd(&g_count[row[e]], 1);
    }
}

// ---------------------------------------------------------------------------
// K3a/b/c: exclusive scan of g_count -> g_rowstart (and cursor copy)
// ---------------------------------------------------------------------------
__global__ void scan1_kernel() {
    __shared__ int s[SCAN_B];
    int i = blockIdx.x * SCAN_B + threadIdx.x;
    int v = (i < N_NODES) ? g_count[i] : 0;
    s[threadIdx.x] = v;
    __syncthreads();
    int x = v;
    #pragma unroll
    for (int o = 1; o < SCAN_B; o <<= 1) {
        int t = (threadIdx.x >= o) ? s[threadIdx.x - o] : 0;
        __syncthreads();
        x += t;
        s[threadIdx.x] = x;
        __syncthreads();
    }
    if (i < N_NODES) g_rowstart[i] = x - v;
    if (threadIdx.x == SCAN_B - 1) g_bsum[blockIdx.x] = x;
}

__global__ void scan2_kernel() {
    if (threadIdx.x == 0) {
        int acc = 0;
        for (int i = 0; i < SCAN_NB; i++) { int t = g_bsum[i]; g_bsum[i] = acc; acc += t; }
    }
}

__global__ void scan3_kernel() {
    int i = blockIdx.x * blockDim.x + threadIdx.x;
    if (i < N_NODES) {
        int v = g_rowstart[i] + g_bsum[i / SCAN_B];
        g_rowstart[i] = v;
        g_cursor[i]   = v;
    }
}

// ---------------------------------------------------------------------------
// K4: per-edge weight + scatter into row-grouped buckets (4 edges/thread)
// ---------------------------------------------------------------------------
__global__ void scatter_kernel(const int* __restrict__ row,
                               const int* __restrict__ col) {
    int t = blockIdx.x * blockDim.x + threadIdx.x;
    int e4 = t * 4;
    if (e4 + 3 < N_EDGES) {
        int4 r = ((const int4*)row)[t];
        int4 c = ((const int4*)col)[t];
        #pragma unroll
        for (int j = 0; j < 4; j++) {
            int rr = (j == 0) ? r.x : (j == 1) ? r.y : (j == 2) ? r.z : r.w;
            int cc = (j == 0) ? c.x : (j == 1) ? c.y : (j == 2) ? c.z : c.w;
            float x = g_ssrc[rr] + g_sdst[cc];
            x = (x > 0.f) ? x : NEG_SLOPE * x;
            float w = __expf(x);
            int p = atomicAdd(&g_cursor[rr], 1);
            g_epack[p] = make_int2(cc, __float_as_int(w));
        }
    } else {
        for (int e = e4; e < N_EDGES; e++) {
            int rr = row[e], cc = col[e];
            float x = g_ssrc[rr] + g_sdst[cc];
            x = (x > 0.f) ? x : NEG_SLOPE * x;
            float w = __expf(x);
            int p = atomicAdd(&g_cursor[rr], 1);
            g_epack[p] = make_int2(cc, __float_as_int(w));
        }
    }
}

// ---------------------------------------------------------------------------
// K5: per-node aggregation. One warp per node; register accumulation.
// ---------------------------------------------------------------------------
__global__ void agg_csr_kernel(float* __restrict__ out) {
    const int warp = (blockIdx.x * blockDim.x + threadIdx.x) >> 5;
    const int lane = threadIdx.x & 31;
    if (warp >= N_NODES) return;

    const int start = g_rowstart[warp];
    const int cnt   = g_count[warp];

    float dsum = 0.f;
    for (int i = lane; i < cnt; i += 32)
        dsum += __int_as_float(g_epack[start + i].y);
    #pragma unroll
    for (int o = 16; o > 0; o >>= 1)
        dsum += __shfl_xor_sync(0xFFFFFFFFu, dsum, o);
    const float inv = 1.f / (dsum + 1e-10f);

    float2 acc = make_float2(0.f, 0.f);
    for (int base = 0; base < cnt; base += 32) {
        int idx = base + lane;
        int2 p = (idx < cnt) ? g_epack[start + idx] : make_int2(0, 0);
        float al_lane = __int_as_float(p.y) * inv;
        int m = cnt - base; if (m > 32) m = 32;
        #pragma unroll 4
        for (int j = 0; j < m; j++) {
            int   c  = __shfl_sync(0xFFFFFFFFu, p.x, j);
            float al = __shfl_sync(0xFFFFFFFFu, al_lane, j);
            float2 v = ((const float2*)g_Wh)[(size_t)c * 32 + lane];
            acc.x = fmaf(al, v.x, acc.x);
            acc.y = fmaf(al, v.y, acc.y);
        }
    }
    ((float2*)out)[(size_t)warp * 32 + lane] = acc;
}

// ---------------------------------------------------------------------------
extern "C" void kernel_launch(void* const* d_in, const int* in_sizes, int n_in,
                              void* d_out, int out_size) {
    const float* h   = (const float*)d_in[0];
    const int*   row = (const int*)d_in[1];
    const int*   col = (const int*)d_in[2];
    const float* W   = (const float*)d_in[3];
    const float* a   = (const float*)d_in[4];
    float*       out = (float*)d_out;

    init_kernel<<<256, 256>>>();
    gemm_s_kernel<<<(N_NODES + 63) / 64, 256>>>(h, W, a);
    hist_kernel<<<(N_EDGES / 4 + 255) / 256, 256>>>(row);
    scan1_kernel<<<SCAN_NB, SCAN_B>>>();
    scan2_kernel<<<1, 32>>>();
    scan3_kernel<<<(N_NODES + 255) / 256, 256>>>();
    scatter_kernel<<<(N_EDGES / 4 + 255) / 256, 256>>>(row, col);
    agg_csr_kernel<<<(N_NODES * 32 + 255) / 256, 256>>>(out);
}

// round 7
// speedup vs baseline: 1.7527x; 1.0791x over previous
#include <cuda_runtime.h>
#include <cuda_fp16.h>

#define N_NODES 100000
#define N_EDGES 1600000
#define IN_DIM  128
#define OUT_DIM 64
#define NEG_SLOPE 0.2f

#define SCAN_B 1024
#define SCAN_NB ((N_NODES + SCAN_B - 1) / SCAN_B)   // 98

// Scratch (static device globals — no allocation allowed)
__device__ __align__(16) __half g_Whh[(size_t)N_NODES * OUT_DIM];  // fp16 copy for gathers
__device__ float g_ssrc[N_NODES];
__device__ float g_sdst[N_NODES];
__device__ int   g_count[N_NODES];
__device__ int   g_rowstart[N_NODES];
__device__ int   g_cursor[N_NODES];
__device__ int   g_bsum[SCAN_NB];
__device__ __align__(8) int2 g_epack[N_EDGES];      // (col, bits(w)) grouped by row

// ---------------------------------------------------------------------------
// K0: zero the histogram
// ---------------------------------------------------------------------------
__global__ void init_kernel() {
    int i = blockIdx.x * blockDim.x + threadIdx.x;
    int stride = gridDim.x * blockDim.x;
    for (int k = i; k < N_NODES; k += stride) g_count[k] = 0;
}

// ---------------------------------------------------------------------------
// K1: Wh = h @ W fused with s_src/s_dst. 64x64 block tile, 4x4 per thread.
// Wh stored as fp16 (gather path); scores computed from f32 registers.
// ---------------------------------------------------------------------------
__global__ void gemm_s_kernel(const float* __restrict__ h,
                              const float* __restrict__ W,
                              const float* __restrict__ a) {
    __shared__ __align__(16) float hs[64][68];
    __shared__ __align__(16) float Ws[64][64];

    const int tid  = threadIdx.x;
    const int tx   = tid & 15;        // col group (4 cols)
    const int ty   = tid >> 4;        // row group (4 rows)
    const int row0 = blockIdx.x * 64;

    float acc[4][4];
    #pragma unroll
    for (int i = 0; i < 4; i++)
        #pragma unroll
        for (int j = 0; j < 4; j++) acc[i][j] = 0.f;

    #pragma unroll
    for (int kc = 0; kc < 2; kc++) {
        #pragma unroll
        for (int p = 0; p < 4; p++) {
            int idx = tid + p * 256;
            int r = idx >> 4, c4 = idx & 15;
            int node = row0 + r;
            float4 v = make_float4(0.f, 0.f, 0.f, 0.f);
            if (node < N_NODES)
                v = ((const float4*)h)[(size_t)node * 32 + kc * 16 + c4];
            *(float4*)&hs[r][c4 * 4] = v;
        }
        #pragma unroll
        for (int p = 0; p < 4; p++) {
            int idx = tid + p * 256;
            int k = idx >> 4, n4 = idx & 15;
            *(float4*)&Ws[k][n4 * 4] =
                ((const float4*)W)[(size_t)(kc * 64 + k) * 16 + n4];
        }
        __syncthreads();

        #pragma unroll 8
        for (int k = 0; k < 64; k++) {
            float4 wv = *(const float4*)&Ws[k][tx * 4];
            float h0 = hs[ty * 4 + 0][k];
            float h1 = hs[ty * 4 + 1][k];
            float h2 = hs[ty * 4 + 2][k];
            float h3 = hs[ty * 4 + 3][k];
            acc[0][0] = fmaf(h0, wv.x, acc[0][0]);
            acc[0][1] = fmaf(h0, wv.y, acc[0][1]);
            acc[0][2] = fmaf(h0, wv.z, acc[0][2]);
            acc[0][3] = fmaf(h0, wv.w, acc[0][3]);
            acc[1][0] = fmaf(h1, wv.x, acc[1][0]);
            acc[1][1] = fmaf(h1, wv.y, acc[1][1]);
            acc[1][2] = fmaf(h1, wv.z, acc[1][2]);
            acc[1][3] = fmaf(h1, wv.w, acc[1][3]);
            acc[2][0] = fmaf(h2, wv.x, acc[2][0]);
            acc[2][1] = fmaf(h2, wv.y, acc[2][1]);
            acc[2][2] = fmaf(h2, wv.z, acc[2][2]);
            acc[2][3] = fmaf(h2, wv.w, acc[2][3]);
            acc[3][0] = fmaf(h3, wv.x, acc[3][0]);
            acc[3][1] = fmaf(h3, wv.y, acc[3][1]);
            acc[3][2] = fmaf(h3, wv.z, acc[3][2]);
            acc[3][3] = fmaf(h3, wv.w, acc[3][3]);
        }
        __syncthreads();
    }

    const float4 as = *(const float4*)&a[tx * 4];
    const float4 ad = *(const float4*)&a[64 + tx * 4];
    float ss[4], sd[4];
    #pragma unroll
    for (int i = 0; i < 4; i++) {
        int node = row0 + ty * 4 + i;
        if (node < N_NODES) {
            __half2 lo = __floats2half2_rn(acc[i][0], acc[i][1]);
            __half2 hi = __floats2half2_rn(acc[i][2], acc[i][3]);
            uint2 pk;
            pk.x = *(unsigned int*)&lo;
            pk.y = *(unsigned int*)&hi;
            ((uint2*)g_Whh)[(size_t)node * 16 + tx] = pk;   // 8B: 4 halfs
        }
        ss[i] = acc[i][0] * as.x + acc[i][1] * as.y + acc[i][2] * as.z + acc[i][3] * as.w;
        sd[i] = acc[i][0] * ad.x + acc[i][1] * ad.y + acc[i][2] * ad.z + acc[i][3] * ad.w;
    }
    #pragma unroll
    for (int o = 8; o > 0; o >>= 1) {
        #pragma unroll
        for (int i = 0; i < 4; i++) {
            ss[i] += __shfl_down_sync(0xFFFFFFFFu, ss[i], o, 16);
            sd[i] += __shfl_down_sync(0xFFFFFFFFu, sd[i], o, 16);
        }
    }
    if (tx == 0) {
        #pragma unroll
        for (int i = 0; i < 4; i++) {
            int node = row0 + ty * 4 + i;
            if (node < N_NODES) { g_ssrc[node] = ss[i]; g_sdst[node] = sd[i]; }
        }
    }
}

// ---------------------------------------------------------------------------
// K2: histogram of row ids (4 edges per thread)
// ---------------------------------------------------------------------------
__global__ void hist_kernel(const int* __restrict__ row) {
    int t = blockIdx.x * blockDim.x + threadIdx.x;
    int e4 = t * 4;
    if (e4 + 3 < N_EDGES) {
        int4 r = ((const int4*)row)[t];
        atomicAdd(&g_count[r.x], 1);
        atomicAdd(&g_count[r.y], 1);
        atomicAdd(&g_count[r.z], 1);
        atomicAdd(&g_count[r.w], 1);
    } else {
        for (int e = e4; e < N_EDGES; e++) atomicAdd(&g_count[row[e]], 1);
    }
}

// ---------------------------------------------------------------------------
// K3a/b/c: exclusive scan of g_count -> g_rowstart (and cursor copy)
// ---------------------------------------------------------------------------
__global__ void scan1_kernel() {
    __shared__ int s[SCAN_B];
    int i = blockIdx.x * SCAN_B + threadIdx.x;
    int v = (i < N_NODES) ? g_count[i] : 0;
    s[threadIdx.x] = v;
    __syncthreads();
    int x = v;
    #pragma unroll
    for (int o = 1; o < SCAN_B; o <<= 1) {
        int t = (threadIdx.x >= o) ? s[threadIdx.x - o] : 0;
        __syncthreads();
        x += t;
        s[threadIdx.x] = x;
        __syncthreads();
    }
    if (i < N_NODES) g_rowstart[i] = x - v;
    if (threadIdx.x == SCAN_B - 1) g_bsum[blockIdx.x] = x;
}

__global__ void scan2_kernel() {
    if (threadIdx.x == 0) {
        int acc = 0;
        for (int i = 0; i < SCAN_NB; i++) { int t = g_bsum[i]; g_bsum[i] = acc; acc += t; }
    }
}

__global__ void scan3_kernel() {
    int i = blockIdx.x * blockDim.x + threadIdx.x;
    if (i < N_NODES) {
        int v = g_rowstart[i] + g_bsum[i / SCAN_B];
        g_rowstart[i] = v;
        g_cursor[i]   = v;
    }
}

// ---------------------------------------------------------------------------
// K4: per-edge weight + scatter into row-grouped buckets (4 edges/thread)
// ---------------------------------------------------------------------------
__global__ void scatter_kernel(const int* __restrict__ row,
                               const int* __restrict__ col) {
    int t = blockIdx.x * blockDim.x + threadIdx.x;
    int e4 = t * 4;
    if (e4 + 3 < N_EDGES) {
        int4 r = ((const int4*)row)[t];
        int4 c = ((const int4*)col)[t];
        #pragma unroll
        for (int j = 0; j < 4; j++) {
            int rr = (j == 0) ? r.x : (j == 1) ? r.y : (j == 2) ? r.z : r.w;
            int cc = (j == 0) ? c.x : (j == 1) ? c.y : (j == 2) ? c.z : c.w;
            float x = g_ssrc[rr] + g_sdst[cc];
            x = (x > 0.f) ? x : NEG_SLOPE * x;
            float w = __expf(x);
            int p = atomicAdd(&g_cursor[rr], 1);
            g_epack[p] = make_int2(cc, __float_as_int(w));
        }
    } else {
        for (int e = e4; e < N_EDGES; e++) {
            int rr = row[e], cc = col[e];
            float x = g_ssrc[rr] + g_sdst[cc];
            x = (x > 0.f) ? x : NEG_SLOPE * x;
            float w = __expf(x);
            int p = atomicAdd(&g_cursor[rr], 1);
            g_epack[p] = make_int2(cc, __float_as_int(w));
        }
    }
}

// ---------------------------------------------------------------------------
// K5: per-node aggregation. One warp per node; fp16 Wh gather, f32 accum.
// ---------------------------------------------------------------------------
__global__ void agg_csr_kernel(float* __restrict__ out) {
    const int warp = (blockIdx.x * blockDim.x + threadIdx.x) >> 5;
    const int lane = threadIdx.x & 31;
    if (warp >= N_NODES) return;

    const int start = g_rowstart[warp];
    const int cnt   = g_count[warp];

    float dsum = 0.f;
    for (int i = lane; i < cnt; i += 32)
        dsum += __int_as_float(__ldg(&g_epack[start + i].y));
    #pragma unroll
    for (int o = 16; o > 0; o >>= 1)
        dsum += __shfl_xor_sync(0xFFFFFFFFu, dsum, o);
    const float inv = 1.f / (dsum + 1e-10f);

    const __half2* Wh2 = (const __half2*)g_Whh;
    float2 acc = make_float2(0.f, 0.f);
    for (int base = 0; base < cnt; base += 32) {
        int idx = base + lane;
        int2 p = (idx < cnt) ? __ldg(&g_epack[start + idx]) : make_int2(0, 0);
        float al_lane = __int_as_float(p.y) * inv;
        int m = cnt - base; if (m > 32) m = 32;
        #pragma unroll 4
        for (int j = 0; j < m; j++) {
            int   c  = __shfl_sync(0xFFFFFFFFu, p.x, j);
            float al = __shfl_sync(0xFFFFFFFFu, al_lane, j);
            float2 v = __half22float2(__ldg(&Wh2[(size_t)c * 32 + lane]));
            acc.x = fmaf(al, v.x, acc.x);
            acc.y = fmaf(al, v.y, acc.y);
        }
    }
    ((float2*)out)[(size_t)warp * 32 + lane] = acc;
}

// ---------------------------------------------------------------------------
extern "C" void kernel_launch(void* const* d_in, const int* in_sizes, int n_in,
                              void* d_out, int out_size) {
    const float* h   = (const float*)d_in[0];
    const int*   row = (const int*)d_in[1];
    const int*   col = (const int*)d_in[2];
    const float* W   = (const float*)d_in[3];
    const float* a   = (const float*)d_in[4];
    float*       out = (float*)d_out;

    init_kernel<<<256, 256>>>();
    gemm_s_kernel<<<(N_NODES + 63) / 64, 256>>>(h, W, a);
    hist_kernel<<<(N_EDGES / 4 + 255) / 256, 256>>>(row);
    scan1_kernel<<<SCAN_NB, SCAN_B>>>();
    scan2_kernel<<<1, 32>>>();
    scan3_kernel<<<(N_NODES + 255) / 256, 256>>>();
    scatter_kernel<<<(N_EDGES / 4 + 255) / 256, 256>>>(row, col);
    agg_csr_kernel<<<(N_NODES * 32 + 255) / 256, 256>>>(out);
}

// round 8
// speedup vs baseline: 1.9476x; 1.1112x over previous
#include <cuda_runtime.h>
#include <cuda_fp16.h>

#define N_NODES 100000
#define N_EDGES 1600000
#define IN_DIM  128
#define OUT_DIM 64
#define NEG_SLOPE 0.2f

#define SCAN_B 1024
#define SCAN_NB ((N_NODES + SCAN_B - 1) / SCAN_B)   // 98
#define GEMM_BLOCKS ((N_NODES + 63) / 64)           // 1563
#define HIST_BLOCKS ((N_EDGES / 4 + 255) / 256)     // 1563

// Scratch (static device globals — no allocation allowed; zero-init at load)
__device__ __align__(16) __half g_Whh[(size_t)N_NODES * OUT_DIM];  // fp16 copy for gathers
__device__ float g_ssrc[N_NODES];
__device__ float g_sdst[N_NODES];
__device__ int   g_count[N_NODES];     // self-cleaning: agg zeroes after use
__device__ int   g_rowstart[N_NODES];
__device__ int   g_cursor[N_NODES];
__device__ int   g_bsum[SCAN_NB];
__device__ __align__(8) int2 g_epack[N_EDGES];      // (col, bits(w)) grouped by row

// ---------------------------------------------------------------------------
// K1: role-split launch. Blocks [0, GEMM_BLOCKS): Wh = h @ W fused with
// s_src/s_dst (64x64 tile, 4x4/thread). Blocks [GEMM_BLOCKS, +HIST): row
// histogram. The two roles use disjoint pipes (FMA vs L2-atomic) and overlap.
// ---------------------------------------------------------------------------
__global__ void gemm_hist_kernel(const float* __restrict__ h,
                                 const float* __restrict__ W,
                                 const float* __restrict__ a,
                                 const int*   __restrict__ row) {
    __shared__ __align__(16) float hs[64][68];
    __shared__ __align__(16) float Ws[64][64];

    const int tid = threadIdx.x;

    if (blockIdx.x >= GEMM_BLOCKS) {
        // ---- histogram role: 4 edges per thread ----
        int t = (blockIdx.x - GEMM_BLOCKS) * blockDim.x + tid;
        int e4 = t * 4;
        if (e4 + 3 < N_EDGES) {
            int4 r = ((const int4*)row)[t];
            atomicAdd(&g_count[r.x], 1);
            atomicAdd(&g_count[r.y], 1);
            atomicAdd(&g_count[r.z], 1);
            atomicAdd(&g_count[r.w], 1);
        } else {
            for (int e = e4; e < N_EDGES; e++) atomicAdd(&g_count[row[e]], 1);
        }
        return;
    }

    // ---- GEMM role ----
    const int tx   = tid & 15;
    const int ty   = tid >> 4;
    const int row0 = blockIdx.x * 64;

    float acc[4][4];
    #pragma unroll
    for (int i = 0; i < 4; i++)
        #pragma unroll
        for (int j = 0; j < 4; j++) acc[i][j] = 0.f;

    #pragma unroll
    for (int kc = 0; kc < 2; kc++) {
        #pragma unroll
        for (int p = 0; p < 4; p++) {
            int idx = tid + p * 256;
            int r = idx >> 4, c4 = idx & 15;
            int node = row0 + r;
            float4 v = make_float4(0.f, 0.f, 0.f, 0.f);
            if (node < N_NODES)
                v = ((const float4*)h)[(size_t)node * 32 + kc * 16 + c4];
            *(float4*)&hs[r][c4 * 4] = v;
        }
        #pragma unroll
        for (int p = 0; p < 4; p++) {
            int idx = tid + p * 256;
            int k = idx >> 4, n4 = idx & 15;
            *(float4*)&Ws[k][n4 * 4] =
                ((const float4*)W)[(size_t)(kc * 64 + k) * 16 + n4];
        }
        __syncthreads();

        #pragma unroll 8
        for (int k = 0; k < 64; k++) {
            float4 wv = *(const float4*)&Ws[k][tx * 4];
            float h0 = hs[ty * 4 + 0][k];
            float h1 = hs[ty * 4 + 1][k];
            float h2 = hs[ty * 4 + 2][k];
            float h3 = hs[ty * 4 + 3][k];
            acc[0][0] = fmaf(h0, wv.x, acc[0][0]);
            acc[0][1] = fmaf(h0, wv.y, acc[0][1]);
            acc[0][2] = fmaf(h0, wv.z, acc[0][2]);
            acc[0][3] = fmaf(h0, wv.w, acc[0][3]);
            acc[1][0] = fmaf(h1, wv.x, acc[1][0]);
            acc[1][1] = fmaf(h1, wv.y, acc[1][1]);
            acc[1][2] = fmaf(h1, wv.z, acc[1][2]);
            acc[1][3] = fmaf(h1, wv.w, acc[1][3]);
            acc[2][0] = fmaf(h2, wv.x, acc[2][0]);
            acc[2][1] = fmaf(h2, wv.y, acc[2][1]);
            acc[2][2] = fmaf(h2, wv.z, acc[2][2]);
            acc[2][3] = fmaf(h2, wv.w, acc[2][3]);
            acc[3][0] = fmaf(h3, wv.x, acc[3][0]);
            acc[3][1] = fmaf(h3, wv.y, acc[3][1]);
            acc[3][2] = fmaf(h3, wv.z, acc[3][2]);
            acc[3][3] = fmaf(h3, wv.w, acc[3][3]);
        }
        __syncthreads();
    }

    const float4 as = *(const float4*)&a[tx * 4];
    const float4 ad = *(const float4*)&a[64 + tx * 4];
    float ss[4], sd[4];
    #pragma unroll
    for (int i = 0; i < 4; i++) {
        int node = row0 + ty * 4 + i;
        if (node < N_NODES) {
            __half2 lo = __floats2half2_rn(acc[i][0], acc[i][1]);
            __half2 hi = __floats2half2_rn(acc[i][2], acc[i][3]);
            uint2 pk;
            pk.x = *(unsigned int*)&lo;
            pk.y = *(unsigned int*)&hi;
            ((uint2*)g_Whh)[(size_t)node * 16 + tx] = pk;
        }
        ss[i] = acc[i][0] * as.x + acc[i][1] * as.y + acc[i][2] * as.z + acc[i][3] * as.w;
        sd[i] = acc[i][0] * ad.x + acc[i][1] * ad.y + acc[i][2] * ad.z + acc[i][3] * ad.w;
    }
    #pragma unroll
    for (int o = 8; o > 0; o >>= 1) {
        #pragma unroll
        for (int i = 0; i < 4; i++) {
            ss[i] += __shfl_down_sync(0xFFFFFFFFu, ss[i], o, 16);
            sd[i] += __shfl_down_sync(0xFFFFFFFFu, sd[i], o, 16);
        }
    }
    if (tx == 0) {
        #pragma unroll
        for (int i = 0; i < 4; i++) {
            int node = row0 + ty * 4 + i;
            if (node < N_NODES) { g_ssrc[node] = ss[i]; g_sdst[node] = sd[i]; }
        }
    }
}

// ---------------------------------------------------------------------------
// K2: block-local exclusive scan of g_count -> g_rowstart, block sums in bsum
// ---------------------------------------------------------------------------
__global__ void scan1_kernel() {
    __shared__ int s[SCAN_B];
    int i = blockIdx.x * SCAN_B + threadIdx.x;
    int v = (i < N_NODES) ? g_count[i] : 0;
    s[threadIdx.x] = v;
    __syncthreads();
    int x = v;
    #pragma unroll
    for (int o = 1; o < SCAN_B; o <<= 1) {
        int t = (threadIdx.x >= o) ? s[threadIdx.x - o] : 0;
        __syncthreads();
        x += t;
        s[threadIdx.x] = x;
        __syncthreads();
    }
    if (i < N_NODES) g_rowstart[i] = x - v;
    if (threadIdx.x == SCAN_B - 1) g_bsum[blockIdx.x] = x;
}

// ---------------------------------------------------------------------------
// K3: add bsum prefix (computed per-block by reduction) + init cursor
// ---------------------------------------------------------------------------
__global__ void scan3_kernel() {
    __shared__ int warp_part[4];
    __shared__ int s_prefix;
    const int b = blockIdx.x;
    const int t = threadIdx.x;

    if (t < 128) {
        int v = (t < b) ? g_bsum[t] : 0;     // b <= 97 < 128
        #pragma unroll
        for (int o = 16; o > 0; o >>= 1)
            v += __shfl_down_sync(0xFFFFFFFFu, v, o);
        if ((t & 31) == 0) warp_part[t >> 5] = v;
    }
    __syncthreads();
    if (t == 0)
        s_prefix = warp_part[0] + warp_part[1] + warp_part[2] + warp_part[3];
    __syncthreads();

    int i = b * SCAN_B + t;
    if (i < N_NODES) {
        int v = g_rowstart[i] + s_prefix;
        g_rowstart[i] = v;
        g_cursor[i]   = v;
    }
}

// ---------------------------------------------------------------------------
// K4: per-edge weight + scatter into row-grouped buckets (4 edges/thread)
// ---------------------------------------------------------------------------
__global__ void scatter_kernel(const int* __restrict__ row,
                               const int* __restrict__ col) {
    int t = blockIdx.x * blockDim.x + threadIdx.x;
    int e4 = t * 4;
    if (e4 + 3 < N_EDGES) {
        int4 r = ((const int4*)row)[t];
        int4 c = ((const int4*)col)[t];
        #pragma unroll
        for (int j = 0; j < 4; j++) {
            int rr = (j == 0) ? r.x : (j == 1) ? r.y : (j == 2) ? r.z : r.w;
            int cc = (j == 0) ? c.x : (j == 1) ? c.y : (j == 2) ? c.z : c.w;
            float x = g_ssrc[rr] + g_sdst[cc];
            x = (x > 0.f) ? x : NEG_SLOPE * x;
            float w = __expf(x);
            int p = atomicAdd(&g_cursor[rr], 1);
            g_epack[p] = make_int2(cc, __float_as_int(w));
        }
    } else {
        for (int e = e4; e < N_EDGES; e++) {
            int rr = row[e], cc = col[e];
            float x = g_ssrc[rr] + g_sdst[cc];
            x = (x > 0.f) ? x : NEG_SLOPE * x;
            float w = __expf(x);
            int p = atomicAdd(&g_cursor[rr], 1);
            g_epack[p] = make_int2(cc, __float_as_int(w));
        }
    }
}

// ---------------------------------------------------------------------------
// K5: per-node aggregation. One warp per node; two edges per step via
// half-warp split (lane loads uint2 = 4 halfs; 16 lanes cover a 64-col row).
// Zeroes g_count after use (self-cleaning for the next graph replay).
// ---------------------------------------------------------------------------
__global__ void agg_csr_kernel(float* __restrict__ out) {
    const int warp = (blockIdx.x * blockDim.x + threadIdx.x) >> 5;
    const int lane = threadIdx.x & 31;
    if (warp >= N_NODES) return;

    const int start = g_rowstart[warp];
    const int cnt   = g_count[warp];

    float dsum = 0.f;
    for (int i = lane; i < cnt; i += 32)
        dsum += __int_as_float(__ldg(&g_epack[start + i].y));
    #pragma unroll
    for (int o = 16; o > 0; o >>= 1)
        dsum += __shfl_xor_sync(0xFFFFFFFFu, dsum, o);
    const float inv = 1.f / (dsum + 1e-10f);

    const int half = lane >> 4;      // 0: even edges, 1: odd edges
    const int hl   = lane & 15;      // lane within half (column group)

    const uint2* Wh4 = (const uint2*)g_Whh;
    float4 acc = make_float4(0.f, 0.f, 0.f, 0.f);

    for (int base = 0; base < cnt; base += 32) {
        int idx = base + lane;
        int2 p = (idx < cnt) ? __ldg(&g_epack[start + idx]) : make_int2(0, 0);
        float al_lane = __int_as_float(p.y) * inv;   // 0 for padding
        int m = cnt - base; if (m > 32) m = 32;
        int nsteps = (m + 1) >> 1;
        #pragma unroll 4
        for (int j = 0; j < nsteps; j++) {
            int src = 2 * j + half;                  // src==m (odd m, half 1) -> padded lane, al=0
            int   c  = __shfl_sync(0xFFFFFFFFu, p.x, src);
            float al = __shfl_sync(0xFFFFFFFFu, al_lane, src);
            uint2 raw = __ldg(&Wh4[(size_t)c * 16 + hl]);
            float2 v0 = __half22float2(*(const __half2*)&raw.x);
            float2 v1 = __half22float2(*(const __half2*)&raw.y);
            acc.x = fmaf(al, v0.x, acc.x);
            acc.y = fmaf(al, v0.y, acc.y);
            acc.z = fmaf(al, v1.x, acc.z);
            acc.w = fmaf(al, v1.y, acc.w);
        }
    }

    // combine even/odd partials: lane l and l+16 hold the same columns
    acc.x += __shfl_xor_sync(0xFFFFFFFFu, acc.x, 16);
    acc.y += __shfl_xor_sync(0xFFFFFFFFu, acc.y, 16);
    acc.z += __shfl_xor_sync(0xFFFFFFFFu, acc.z, 16);
    acc.w += __shfl_xor_sync(0xFFFFFFFFu, acc.w, 16);

    if (half == 0)
        ((float4*)out)[(size_t)warp * 16 + hl] = acc;

    if (lane == 0) g_count[warp] = 0;   // self-clean for next invocation
}

// ---------------------------------------------------------------------------
extern "C" void kernel_launch(void* const* d_in, const int* in_sizes, int n_in,
                              void* d_out, int out_size) {
    const float* h   = (const float*)d_in[0];
    const int*   row = (const int*)d_in[1];
    const int*   col = (const int*)d_in[2];
    const float* W   = (const float*)d_in[3];
    const float* a   = (const float*)d_in[4];
    float*       out = (float*)d_out;

    gemm_hist_kernel<<<GEMM_BLOCKS + HIST_BLOCKS, 256>>>(h, W, a, row);
    scan1_kernel<<<SCAN_NB, SCAN_B>>>();
    scan3_kernel<<<SCAN_NB, SCAN_B>>>();
    scatter_kernel<<<HIST_BLOCKS, 256>>>(row, col);
    agg_csr_kernel<<<(N_NODES * 32 + 255) / 256, 256>>>(out);
}